// round 1
// baseline (speedup 1.0000x reference)
#include <cuda_runtime.h>
#include <cuda_bf16.h>
#include <math.h>

// Problem constants
#define BB 4
#define SS 2048
#define EE 128
#define HH 4
#define HD 32
#define NTOK (BB*SS)          // 8192
#define NBH  (BB*HH)          // 16

// Scratch (device globals: allocation-free rule)
__device__ float g_X[NTOK*512];     // zero-padded RKT input [8192,512]
__device__ float g_Q256[NTOK*256];  // query concat [8192,256]
__device__ float g_H[NTOK*256];     // relu(X@Win+b) [8192,256]
__device__ float g_q[NBH*SS*HD];    // [B*H, S, 32]
__device__ float g_k[NBH*SS*HD];
__device__ float g_v[NBH*SS*HD];
__device__ float g_o[NBH*SS*HD];    // attention output per head

// ---------------------------------------------------------------------------
// Kernel 1: build X512 and Q256 from embedding gathers
// grid = 8192 blocks, 128 threads
// ---------------------------------------------------------------------------
__global__ void build_kernel(const int* __restrict__ item_in,
                             const int* __restrict__ skill_in,
                             const int* __restrict__ label_in,
                             const int* __restrict__ item_ids,
                             const int* __restrict__ skill_ids,
                             const float* __restrict__ item_emb,
                             const float* __restrict__ skill_emb)
{
    int t = blockIdx.x;
    int d = threadIdx.x; // 0..127
    int lb = label_in[t];
    float itv = item_emb[(size_t)item_in[t]*EE + d];
    float skv = skill_emb[(size_t)skill_in[t]*EE + d];
    float* x = g_X + (size_t)t*512;
    x[d]       = lb ? itv : 0.f;
    x[128 + d] = lb ? 0.f : itv;
    x[256 + d] = lb ? skv : 0.f;
    x[384 + d] = lb ? 0.f : skv;
    float* qx = g_Q256 + (size_t)t*256;
    qx[d]       = item_emb[(size_t)item_ids[t]*EE + d];
    qx[128 + d] = skill_emb[(size_t)skill_ids[t]*EE + d];
}

// ---------------------------------------------------------------------------
// Kernel 2: tiled SGEMM, C = act(A @ W + bias)
// A selected from device globals (asel: 0=g_X, 1=g_Q256, 2=g_H)
// osel: 0 = relu into g_H[8192,256]; 1/2/3 = scatter to g_q/g_k/g_v [B*H,S,32]
// BM=BN=64, BK=16, 256 threads, 4x4 per thread
// ---------------------------------------------------------------------------
__global__ __launch_bounds__(256) void sgemm_kernel(
    const float* __restrict__ W, const float* __restrict__ bias,
    int K, int N, int asel, int osel)
{
    __shared__ float As[16*68];   // [k][m] transposed, padded
    __shared__ float Ws[16*64];   // [k][n]

    const float* A = (asel == 0) ? g_X : (asel == 1) ? g_Q256 : g_H;

    int tid = threadIdx.x;
    int bx = blockIdx.x, by = blockIdx.y;
    int tx = tid & 15, ty = tid >> 4;

    float acc[4][4];
    #pragma unroll
    for (int i = 0; i < 4; i++)
        #pragma unroll
        for (int j = 0; j < 4; j++) acc[i][j] = 0.f;

    int arow  = tid >> 2;           // 0..63
    int acol4 = (tid & 3) * 4;      // 0,4,8,12
    int wrow  = tid >> 4;           // 0..15
    int wcol4 = (tid & 15) * 4;     // 0..60

    const float* Aptr = A + ((size_t)(by*64 + arow))*K + acol4;
    const float* Wptr = W + (size_t)wrow*N + bx*64 + wcol4;

    for (int kk = 0; kk < K; kk += 16) {
        float4 av = *(const float4*)(Aptr + kk);
        float4 wv = *(const float4*)(Wptr + (size_t)kk*N);
        __syncthreads();
        As[(acol4+0)*68 + arow] = av.x;
        As[(acol4+1)*68 + arow] = av.y;
        As[(acol4+2)*68 + arow] = av.z;
        As[(acol4+3)*68 + arow] = av.w;
        *(float4*)&Ws[wrow*64 + wcol4] = wv;
        __syncthreads();
        #pragma unroll
        for (int k = 0; k < 16; k++) {
            float4 a = *(const float4*)&As[k*68 + ty*4];
            float4 b = *(const float4*)&Ws[k*64 + tx*4];
            float ar[4] = {a.x, a.y, a.z, a.w};
            float br[4] = {b.x, b.y, b.z, b.w};
            #pragma unroll
            for (int i = 0; i < 4; i++)
                #pragma unroll
                for (int j = 0; j < 4; j++)
                    acc[i][j] += ar[i] * br[j];
        }
    }

    int m0 = by*64 + ty*4, n0 = bx*64 + tx*4;
    #pragma unroll
    for (int i = 0; i < 4; i++) {
        #pragma unroll
        for (int j = 0; j < 4; j++) {
            float v = acc[i][j] + bias[n0 + j];
            int m = m0 + i, n = n0 + j;
            if (osel == 0) {
                g_H[(size_t)m*256 + n] = fmaxf(v, 0.f);
            } else {
                float* o = (osel == 1) ? g_q : (osel == 2) ? g_k : g_v;
                int bb = m >> 11, s = m & 2047;
                int h = n >> 5, hd = n & 31;
                o[(((size_t)(bb*HH + h))*SS + s)*HD + hd] = v;
            }
        }
    }
}

// ---------------------------------------------------------------------------
// Block reductions over 256 threads (3 values at once)
// ---------------------------------------------------------------------------
__device__ __forceinline__ void blockReduce3Max(float& a, float& b, float& c,
                                                float* red, int tid)
{
    #pragma unroll
    for (int o = 16; o; o >>= 1) {
        a = fmaxf(a, __shfl_xor_sync(0xffffffffu, a, o));
        b = fmaxf(b, __shfl_xor_sync(0xffffffffu, b, o));
        c = fmaxf(c, __shfl_xor_sync(0xffffffffu, c, o));
    }
    int w = tid >> 5;
    if ((tid & 31) == 0) { red[w] = a; red[8+w] = b; red[16+w] = c; }
    __syncthreads();
    if (tid == 0) {
        float ra = red[0], rb = red[8], rc = red[16];
        #pragma unroll
        for (int i = 1; i < 8; i++) {
            ra = fmaxf(ra, red[i]); rb = fmaxf(rb, red[8+i]); rc = fmaxf(rc, red[16+i]);
        }
        red[24] = ra; red[25] = rb; red[26] = rc;
    }
    __syncthreads();
    a = red[24]; b = red[25]; c = red[26];
}

__device__ __forceinline__ void blockReduce3Sum(float& a, float& b, float& c,
                                                float* red, int tid)
{
    #pragma unroll
    for (int o = 16; o; o >>= 1) {
        a += __shfl_xor_sync(0xffffffffu, a, o);
        b += __shfl_xor_sync(0xffffffffu, b, o);
        c += __shfl_xor_sync(0xffffffffu, c, o);
    }
    int w = tid >> 5;
    if ((tid & 31) == 0) { red[w] = a; red[8+w] = b; red[16+w] = c; }
    __syncthreads();
    if (tid == 0) {
        float ra = red[0], rb = red[8], rc = red[16];
        #pragma unroll
        for (int i = 1; i < 8; i++) { ra += red[i]; rb += red[8+i]; rc += red[16+i]; }
        red[24] = ra; red[25] = rb; red[26] = rc;
    }
    __syncthreads();
    a = red[24]; b = red[25]; c = red[26];
}

// ---------------------------------------------------------------------------
// Kernel 3: fused attention.
// grid = (128 qtiles, 16 bh), 256 threads, TQ=16 q-rows per block.
// SMEM: Ssc[16][2048] scores->probs | KV tile [128][33] | Trow/Rrow[2048] | red
// ---------------------------------------------------------------------------
#define TQ 16
#define KT 128
#define SMEM_FLOATS (TQ*SS + KT*33 + SS + SS + 32)
#define SMEM_BYTES  (SMEM_FLOATS*4)

__global__ __launch_bounds__(256) void attn_kernel(
    const float* __restrict__ rel, const float* __restrict__ ts,
    const float* __restrict__ l1p, const float* __restrict__ l2p,
    float* __restrict__ prob_out)
{
    extern __shared__ float sm[];
    float* Ssc  = sm;                  // TQ*2048
    float* KVs  = sm + TQ*SS;          // 128*33
    float* Trow = KVs + KT*33;         // 2048
    float* Rrow = Trow + SS;           // 2048
    float* Red  = Rrow + SS;           // 32

    const int tid = threadIdx.x;
    const int qt  = blockIdx.x;
    const int bh  = blockIdx.y;
    const int q0  = qt * TQ;
    const int b   = bh >> 2;

    const float l1 = *l1p, l2 = *l2p;
    const float c_p = (1.f - l1) * (1.f - l2);
    const float c_t = (1.f - l1) * l2;
    const float c_r = l1;
    const float scale = 0.17677669529663687f; // 1/sqrt(32)

    // ---------- Phase 1: scores = QK^T/sqrt(HD), masked ----------
    const int klane = tid & 31;
    const int rp    = tid >> 5;        // 0..7 -> rows rp, rp+8
    const int qg0   = q0 + rp;
    const int qg1   = q0 + rp + 8;

    const float* qb = g_q + (size_t)bh*SS*HD;
    float q0r[32], q1r[32];
    #pragma unroll
    for (int d = 0; d < 32; d++) {
        q0r[d] = qb[(size_t)qg0*HD + d];
        q1r[d] = qb[(size_t)qg1*HD + d];
    }
    const float* kb = g_k + (size_t)bh*SS*HD;

    for (int kt = 0; kt < SS/KT; kt++) {
        const float4* src = (const float4*)(kb + (size_t)kt*KT*HD);
        __syncthreads();
        #pragma unroll
        for (int w = 0; w < 4; w++) {
            int idx4 = tid + 256*w;
            float4 v = src[idx4];
            int k  = idx4 >> 3;
            int d4 = (idx4 & 7) * 4;
            KVs[k*33 + d4 + 0] = v.x;
            KVs[k*33 + d4 + 1] = v.y;
            KVs[k*33 + d4 + 2] = v.z;
            KVs[k*33 + d4 + 3] = v.w;
        }
        __syncthreads();
        #pragma unroll
        for (int j = 0; j < 4; j++) {
            int kloc = klane + 32*j;
            int kg = kt*KT + kloc;
            float s0 = 0.f, s1 = 0.f;
            #pragma unroll
            for (int d = 0; d < 32; d++) {
                float kv = KVs[kloc*33 + d];
                s0 += q0r[d] * kv;
                s1 += q1r[d] * kv;
            }
            Ssc[rp*SS + kg]     = (kg > qg0) ? -1e9f : s0 * scale;
            Ssc[(rp+8)*SS + kg] = (kg > qg1) ? -1e9f : s1 * scale;
        }
    }
    __syncthreads();

    // ---------- Phase 2: three softmaxes + mix, row by row ----------
    for (int i = 0; i < TQ; i++) {
        const int q = q0 + i;
        const float* relrow = rel + ((size_t)b*SS + q)*SS;
        const float* tsrow  = ts  + ((size_t)b*SS + q)*SS;

        float ms = -INFINITY, mt = -INFINITY, mr = -INFINITY;
        #pragma unroll
        for (int j = 0; j < 8; j++) {
            int k = tid + 256*j;
            float s = Ssc[i*SS + k];
            ms = fmaxf(ms, s);
            float z = (k <= q) ? __expf(-fabsf(tsrow[k])) : -INFINITY;
            Trow[k] = z;
            mt = fmaxf(mt, z);
            float rv = relrow[k];
            float rr = (k > q && rv != 0.f) ? rv : -10000.f;
            Rrow[k] = rr;
            mr = fmaxf(mr, rr);
        }
        blockReduce3Max(ms, mt, mr, Red, tid);

        float Zs = 0.f, Zt = 0.f, Zr = 0.f;
        #pragma unroll
        for (int j = 0; j < 8; j++) {
            int k = tid + 256*j;
            float es = __expf(Ssc[i*SS + k] - ms);
            Ssc[i*SS + k] = es; Zs += es;
            float et = __expf(Trow[k] - mt);
            Trow[k] = et; Zt += et;
            float er = __expf(Rrow[k] - mr);
            Rrow[k] = er; Zr += er;
        }
        blockReduce3Sum(Zs, Zt, Zr, Red, tid);

        const float ip = c_p / Zs, it = c_t / Zt, ir = c_r / Zr;
        float* orow = prob_out + ((size_t)bh*SS + q)*SS;
        #pragma unroll
        for (int j = 0; j < 8; j++) {
            int k = tid + 256*j;
            float pv = Ssc[i*SS + k]*ip + Trow[k]*it + Rrow[k]*ir;
            Ssc[i*SS + k] = pv;
            orow[k] = pv;
        }
        __syncthreads();
    }

    // ---------- Phase 3: out = prob @ V ----------
    const int d  = tid & 31;
    const int ig = tid >> 5;   // rows ig, ig+8
    float acc0 = 0.f, acc1 = 0.f;
    const float* vb = g_v + (size_t)bh*SS*HD;

    for (int kt = 0; kt < SS/KT; kt++) {
        const float4* src = (const float4*)(vb + (size_t)kt*KT*HD);
        __syncthreads();
        #pragma unroll
        for (int w = 0; w < 4; w++) {
            int idx4 = tid + 256*w;
            float4 v = src[idx4];
            int k  = idx4 >> 3;
            int d4 = (idx4 & 7) * 4;
            KVs[k*33 + d4 + 0] = v.x;
            KVs[k*33 + d4 + 1] = v.y;
            KVs[k*33 + d4 + 2] = v.z;
            KVs[k*33 + d4 + 3] = v.w;
        }
        __syncthreads();
        const int kbase = kt*KT;
        #pragma unroll 8
        for (int kloc = 0; kloc < KT; kloc += 2) {
            float2 pa = *(const float2*)&Ssc[ig*SS + kbase + kloc];
            float2 pb = *(const float2*)&Ssc[(ig+8)*SS + kbase + kloc];
            float v0 = KVs[kloc*33 + d];
            float v1 = KVs[(kloc+1)*33 + d];
            acc0 += pa.x*v0 + pa.y*v1;
            acc1 += pb.x*v0 + pb.y*v1;
        }
    }
    g_o[((size_t)bh*SS + q0 + ig)*HD + d]     = acc0;
    g_o[((size_t)bh*SS + q0 + ig + 8)*HD + d] = acc1;
}

// ---------------------------------------------------------------------------
// Kernel 4: pred = out @ Wout + bout   (out regrouped from [B,H,S,32])
// grid = 8192 blocks, 128 threads
// ---------------------------------------------------------------------------
__global__ void pred_kernel(const float* __restrict__ Wout,
                            const float* __restrict__ bout,
                            float* __restrict__ pred)
{
    int t = blockIdx.x;
    int d = threadIdx.x; // 0..127
    int bb = t >> 11, s = t & 2047;
    int h = d >> 5, hd = d & 31;
    float v = g_o[(((size_t)(bb*HH + h))*SS + s)*HD + hd] * Wout[d];
    __shared__ float red[4];
    #pragma unroll
    for (int o = 16; o; o >>= 1) v += __shfl_xor_sync(0xffffffffu, v, o);
    if ((d & 31) == 0) red[d >> 5] = v;
    __syncthreads();
    if (d == 0) pred[t] = red[0] + red[1] + red[2] + red[3] + bout[0];
}

// ---------------------------------------------------------------------------
extern "C" void kernel_launch(void* const* d_in, const int* in_sizes, int n_in,
                              void* d_out, int out_size)
{
    const int*   item_in   = (const int*)  d_in[0];
    const int*   skill_in  = (const int*)  d_in[1];
    const int*   label_in  = (const int*)  d_in[2];
    const int*   item_ids  = (const int*)  d_in[3];
    const int*   skill_ids = (const int*)  d_in[4];
    const float* rel       = (const float*)d_in[5];
    const float* ts        = (const float*)d_in[6];
    const float* item_emb  = (const float*)d_in[7];
    const float* skill_emb = (const float*)d_in[8];
    const float* Win       = (const float*)d_in[9];
    const float* b_in      = (const float*)d_in[10];
    const float* Wq        = (const float*)d_in[11];
    const float* bq        = (const float*)d_in[12];
    const float* Wk        = (const float*)d_in[13];
    const float* bk        = (const float*)d_in[14];
    const float* Wv        = (const float*)d_in[15];
    const float* bv        = (const float*)d_in[16];
    const float* Wout      = (const float*)d_in[17];
    const float* bout      = (const float*)d_in[18];
    const float* l1        = (const float*)d_in[19];
    const float* l2        = (const float*)d_in[20];

    float* pred = (float*)d_out;          // [B,S,1] = 8192
    float* prob = pred + NTOK;            // [B,H,S,S]

    cudaFuncSetAttribute(attn_kernel,
                         cudaFuncAttributeMaxDynamicSharedMemorySize,
                         SMEM_BYTES);

    build_kernel<<<NTOK, 128>>>(item_in, skill_in, label_in, item_ids,
                                skill_ids, item_emb, skill_emb);

    // H = relu(X @ Win + b_in)
    sgemm_kernel<<<dim3(4, 128), 256>>>(Win, b_in, 512, 256, 0, 0);
    // q = Q256 @ Wq + bq  (scatter to [B,H,S,32])
    sgemm_kernel<<<dim3(2, 128), 256>>>(Wq, bq, 256, 128, 1, 1);
    // k = H @ Wk + bk
    sgemm_kernel<<<dim3(2, 128), 256>>>(Wk, bk, 256, 128, 2, 2);
    // v = H @ Wv + bv
    sgemm_kernel<<<dim3(2, 128), 256>>>(Wv, bv, 256, 128, 2, 3);

    attn_kernel<<<dim3(SS/TQ, NBH), 256, SMEM_BYTES>>>(rel, ts, l1, l2, prob);

    pred_kernel<<<NTOK, 128>>>(Wout, bout, pred);
}

// round 2
// speedup vs baseline: 1.3983x; 1.3983x over previous
#include <cuda_runtime.h>
#include <cuda_bf16.h>
#include <math.h>

// Problem constants
#define BB 4
#define SS 2048
#define EE 128
#define HH 4
#define HD 32
#define NTOK (BB*SS)          // 8192
#define NBH  (BB*HH)          // 16

// Scratch (device globals: allocation-free rule)
__device__ float        g_X[NTOK*512];      // zero-padded RKT input [8192,512]
__device__ float        g_Q256[NTOK*256];   // query concat [8192,256]
__device__ float        g_H[NTOK*256];      // relu(X@Win+b) [8192,256]
__device__ unsigned int g_qb[NBH*SS*16];    // q bf16x2 [B*H,S,16]
__device__ unsigned int g_kb[NBH*SS*16];    // k bf16x2
__device__ float        g_v[NBH*SS*HD];     // v f32 [B*H,S,32]
__device__ float        g_o[NBH*SS*HD];     // attention output
__device__ float        g_base[(size_t)BB*SS*SS]; // c_t*time_attn + c_r*rel_attn

// ---------------------------------------------------------------------------
// f32x2 packed-math helpers
// ---------------------------------------------------------------------------
__device__ __forceinline__ void ffma2(unsigned long long& d,
                                      unsigned long long a, unsigned long long b) {
    asm("fma.rn.f32x2 %0, %1, %2, %0;" : "+l"(d) : "l"(a), "l"(b));
}
__device__ __forceinline__ unsigned long long bcast2(float x) {
    unsigned long long r;
    asm("mov.b64 %0, {%1, %1};" : "=l"(r) : "f"(x));
    return r;
}
__device__ __forceinline__ float2 unpack2(unsigned long long v) {
    float2 f;
    asm("mov.b64 {%0, %1}, %2;" : "=f"(f.x), "=f"(f.y) : "l"(v));
    return f;
}

// ---------------------------------------------------------------------------
// Kernel 1: build X512 and Q256 from embedding gathers
// ---------------------------------------------------------------------------
__global__ void build_kernel(const int* __restrict__ item_in,
                             const int* __restrict__ skill_in,
                             const int* __restrict__ label_in,
                             const int* __restrict__ item_ids,
                             const int* __restrict__ skill_ids,
                             const float* __restrict__ item_emb,
                             const float* __restrict__ skill_emb)
{
    int t = blockIdx.x;
    int d = threadIdx.x; // 0..127
    int lb = label_in[t];
    float itv = item_emb[(size_t)item_in[t]*EE + d];
    float skv = skill_emb[(size_t)skill_in[t]*EE + d];
    float* x = g_X + (size_t)t*512;
    x[d]       = lb ? itv : 0.f;
    x[128 + d] = lb ? 0.f : itv;
    x[256 + d] = lb ? skv : 0.f;
    x[384 + d] = lb ? 0.f : skv;
    float* qx = g_Q256 + (size_t)t*256;
    qx[d]       = item_emb[(size_t)item_ids[t]*EE + d];
    qx[128 + d] = skill_emb[(size_t)skill_ids[t]*EE + d];
}

// ---------------------------------------------------------------------------
// Kernel 2: precompute base = c_t*time_attn + c_r*rel_attn  (head-invariant!)
// grid = 8192 (one (b,q) row), 256 threads
// ---------------------------------------------------------------------------
__global__ __launch_bounds__(256) void base_kernel(const float* __restrict__ ts,
                                                   const float* __restrict__ rel,
                                                   const float* __restrict__ l1p,
                                                   const float* __restrict__ l2p)
{
    __shared__ float et[SS];
    __shared__ float er[SS];
    __shared__ float red[32];

    const int tid = threadIdx.x;
    const int row = blockIdx.x;
    const int q = row & (SS-1);
    const float l1 = *l1p, l2 = *l2p;

    const float* tsrow  = ts  + (size_t)row*SS;
    const float* relrow = rel + (size_t)row*SS;

    float st = 0.f, mr = -1e30f;
    #pragma unroll
    for (int j = 0; j < 8; j++) {
        int k = tid + 256*j;
        float tv = tsrow[k];
        float e1 = (k <= q) ? __expf(__expf(-fabsf(tv))) : 0.f;
        et[k] = e1; st += e1;
        float rv = relrow[k];
        float rr = (k > q && rv != 0.f) ? rv : -10000.f;
        er[k] = rr; mr = fmaxf(mr, rr);
    }
    #pragma unroll
    for (int o = 16; o; o >>= 1) {
        st += __shfl_xor_sync(0xffffffffu, st, o);
        mr  = fmaxf(mr, __shfl_xor_sync(0xffffffffu, mr, o));
    }
    if ((tid & 31) == 0) { red[tid>>5] = st; red[8 + (tid>>5)] = mr; }
    __syncthreads();
    if (tid == 0) {
        float s = 0.f, m = -1e30f;
        #pragma unroll
        for (int i = 0; i < 8; i++) { s += red[i]; m = fmaxf(m, red[8+i]); }
        red[16] = s; red[17] = m;
    }
    __syncthreads();
    st = red[16]; mr = red[17];

    float sr = 0.f;
    #pragma unroll
    for (int j = 0; j < 8; j++) {
        int k = tid + 256*j;
        float e = __expf(er[k] - mr);
        er[k] = e; sr += e;
    }
    #pragma unroll
    for (int o = 16; o; o >>= 1) sr += __shfl_xor_sync(0xffffffffu, sr, o);
    if ((tid & 31) == 0) red[tid>>5] = sr;
    __syncthreads();
    if (tid == 0) {
        float s = 0.f;
        #pragma unroll
        for (int i = 0; i < 8; i++) s += red[i];
        red[18] = s;
    }
    __syncthreads();
    sr = red[18];

    const float ct = (1.f - l1) * l2 / st;
    const float cr = l1 / sr;
    float* brow = g_base + (size_t)row*SS;
    #pragma unroll
    for (int j = 0; j < 8; j++) {
        int k = tid + 256*j;
        brow[k] = fmaf(ct, et[k], cr * er[k]);
    }
}

// ---------------------------------------------------------------------------
// Kernel 3: tiled SGEMM with z-dispatch over up to 3 weight sets.
// osel = obase + blockIdx.z:
//   0: g_X @ W -> relu -> g_H        (K=512, N=256)
//   1: g_Q256 @ Wq -> bf16 g_qb      (K=256, N=128)
//   2: g_H @ Wk -> bf16 g_kb
//   3: g_H @ Wv -> f32 g_v
// ---------------------------------------------------------------------------
__global__ __launch_bounds__(256) void sgemm_kernel(
    const float* __restrict__ W0, const float* __restrict__ B0,
    const float* __restrict__ W1, const float* __restrict__ B1,
    const float* __restrict__ W2, const float* __restrict__ B2,
    int K, int N, int obase)
{
    __shared__ float As[16*68];
    __shared__ float Ws[16*64];

    const int z = blockIdx.z;
    const float* W    = (z == 0) ? W0 : (z == 1) ? W1 : W2;
    const float* bias = (z == 0) ? B0 : (z == 1) ? B1 : B2;
    const int osel = obase + z;
    const float* A = (osel == 0) ? g_X : (osel == 1) ? g_Q256 : g_H;

    int tid = threadIdx.x;
    int bx = blockIdx.x, by = blockIdx.y;
    int tx = tid & 15, ty = tid >> 4;

    float acc[4][4];
    #pragma unroll
    for (int i = 0; i < 4; i++)
        #pragma unroll
        for (int j = 0; j < 4; j++) acc[i][j] = 0.f;

    int arow  = tid >> 2;
    int acol4 = (tid & 3) * 4;
    int wrow  = tid >> 4;
    int wcol4 = (tid & 15) * 4;

    const float* Aptr = A + ((size_t)(by*64 + arow))*K + acol4;
    const float* Wptr = W + (size_t)wrow*N + bx*64 + wcol4;

    for (int kk = 0; kk < K; kk += 16) {
        float4 av = *(const float4*)(Aptr + kk);
        float4 wv = *(const float4*)(Wptr + (size_t)kk*N);
        __syncthreads();
        As[(acol4+0)*68 + arow] = av.x;
        As[(acol4+1)*68 + arow] = av.y;
        As[(acol4+2)*68 + arow] = av.z;
        As[(acol4+3)*68 + arow] = av.w;
        *(float4*)&Ws[wrow*64 + wcol4] = wv;
        __syncthreads();
        #pragma unroll
        for (int k = 0; k < 16; k++) {
            float4 a = *(const float4*)&As[k*68 + ty*4];
            float4 bq = *(const float4*)&Ws[k*64 + tx*4];
            float ar[4] = {a.x, a.y, a.z, a.w};
            float br[4] = {bq.x, bq.y, bq.z, bq.w};
            #pragma unroll
            for (int i = 0; i < 4; i++)
                #pragma unroll
                for (int j = 0; j < 4; j++)
                    acc[i][j] += ar[i] * br[j];
        }
    }

    int m0 = by*64 + ty*4, n0 = bx*64 + tx*4;
    if (osel == 0) {
        #pragma unroll
        for (int i = 0; i < 4; i++)
            #pragma unroll
            for (int j = 0; j < 4; j++)
                g_H[(size_t)(m0+i)*256 + n0 + j] = fmaxf(acc[i][j] + bias[n0+j], 0.f);
    } else if (osel == 3) {
        #pragma unroll
        for (int i = 0; i < 4; i++) {
            int m = m0 + i, bb = m >> 11, s = m & (SS-1);
            int h = n0 >> 5, hd = n0 & 31;
            float* o = g_v + (((size_t)(bb*HH + h))*SS + s)*HD + hd;
            #pragma unroll
            for (int j = 0; j < 4; j++) o[j] = acc[i][j] + bias[n0+j];
        }
    } else {
        unsigned int* dstbase = (osel == 1) ? g_qb : g_kb;
        #pragma unroll
        for (int i = 0; i < 4; i++) {
            int m = m0 + i, bb = m >> 11, s = m & (SS-1);
            int h = n0 >> 5, hd = n0 & 31;
            float v0 = acc[i][0] + bias[n0+0];
            float v1 = acc[i][1] + bias[n0+1];
            float v2 = acc[i][2] + bias[n0+2];
            float v3 = acc[i][3] + bias[n0+3];
            __nv_bfloat162 p0 = __floats2bfloat162_rn(v0, v1);
            __nv_bfloat162 p1 = __floats2bfloat162_rn(v2, v3);
            unsigned int* dst = dstbase + (((size_t)(bb*HH + h))*SS + s)*16 + (hd >> 1);
            dst[0] = reinterpret_cast<unsigned int&>(p0);
            dst[1] = reinterpret_cast<unsigned int&>(p1);
        }
    }
}

// ---------------------------------------------------------------------------
// Kernel 4: fused attention. grid = (16 bh, 128 qtiles), 512 threads.
// SMEM: Ssc[16][2064] (scores->probs) | KV tile (bf16 k / f32 v, reused)
// ---------------------------------------------------------------------------
#define TQ 16
#define KT 128
#define SSTR 2064
#define ATTN_SMEM ((TQ*SSTR + KT*36)*4)

__global__ __launch_bounds__(512, 1) void attn_kernel(
    const float* __restrict__ l1p, const float* __restrict__ l2p,
    float* __restrict__ prob)
{
    extern __shared__ float sm[];
    float* Ssc = sm;
    float* KVf = sm + TQ*SSTR;
    unsigned int* KVu = (unsigned int*)KVf;

    const int tid = threadIdx.x;
    const int bh = blockIdx.x;
    const int q0 = blockIdx.y * TQ;
    const int b  = bh >> 2;
    const int w = tid >> 5, lane = tid & 31;

    // ---------- Phase 1: scores = (q@k^T)/sqrt(HD), bf16 HFMA2 ----------
    {
        const int r0 = (w & 7) * 2, r1 = r0 + 1;
        const int khalf = (w >> 3) * 64;
        const int qg0 = q0 + r0, qg1 = q0 + r1;

        unsigned int q0u[16], q1u[16];
        const uint4* qp0 = (const uint4*)(g_qb + ((size_t)bh*SS + qg0)*16);
        const uint4* qp1 = (const uint4*)(g_qb + ((size_t)bh*SS + qg1)*16);
        #pragma unroll
        for (int i = 0; i < 4; i++) {
            uint4 t0 = qp0[i];
            q0u[4*i+0]=t0.x; q0u[4*i+1]=t0.y; q0u[4*i+2]=t0.z; q0u[4*i+3]=t0.w;
            uint4 t1 = qp1[i];
            q1u[4*i+0]=t1.x; q1u[4*i+1]=t1.y; q1u[4*i+2]=t1.z; q1u[4*i+3]=t1.w;
        }
        const __nv_bfloat162* q0h = (const __nv_bfloat162*)q0u;
        const __nv_bfloat162* q1h = (const __nv_bfloat162*)q1u;
        const float scale = 0.17677669529663687f;

        for (int t = 0; t < SS/KT; t++) {
            __syncthreads();
            {
                const uint4* src = (const uint4*)(g_kb + ((size_t)bh*SS + t*KT)*16);
                uint4 vk = src[tid];
                int kk = tid >> 2, qd = (tid & 3) * 4;
                *(uint4*)&KVu[kk*20 + qd] = vk;
            }
            __syncthreads();
            #pragma unroll
            for (int j = 0; j < 2; j++) {
                int kloc = khalf + j*32 + lane;
                const uint4* kp = (const uint4*)&KVu[kloc*20];
                uint4 ka = kp[0], kb4 = kp[1], kc = kp[2], kd = kp[3];
                unsigned int kvu[16] = {ka.x,ka.y,ka.z,ka.w, kb4.x,kb4.y,kb4.z,kb4.w,
                                        kc.x,kc.y,kc.z,kc.w, kd.x,kd.y,kd.z,kd.w};
                const __nv_bfloat162* kh = (const __nv_bfloat162*)kvu;
                __nv_bfloat162 a0 = __floats2bfloat162_rn(0.f, 0.f);
                __nv_bfloat162 a1 = a0;
                #pragma unroll
                for (int i = 0; i < 16; i++) {
                    a0 = __hfma2(q0h[i], kh[i], a0);
                    a1 = __hfma2(q1h[i], kh[i], a1);
                }
                float2 f0 = __bfloat1622float2(a0);
                float2 f1 = __bfloat1622float2(a1);
                int kg = t*KT + kloc;
                float s0 = (f0.x + f0.y) * scale;
                float s1 = (f1.x + f1.y) * scale;
                Ssc[r0*SSTR + kg] = (kg > qg0) ? -1e9f : s0;
                Ssc[r1*SSTR + kg] = (kg > qg1) ? -1e9f : s1;
            }
        }
    }
    __syncthreads();

    // ---------- Phase 2: QK softmax + mix with precomputed base ----------
    {
        const float l1 = *l1p, l2 = *l2p;
        const float cp = (1.f - l1) * (1.f - l2);
        const int q = q0 + w;             // one row per warp
        float* srow = Ssc + w*SSTR;
        float zs = 0.f;
        #pragma unroll 4
        for (int j = 0; j < 64; j++) {
            int k = j*32 + lane;
            float e = __expf(srow[k]);
            srow[k] = e; zs += e;
        }
        #pragma unroll
        for (int o = 16; o; o >>= 1) zs += __shfl_xor_sync(0xffffffffu, zs, o);
        const float ip = cp / zs;
        const float* brow = g_base + ((size_t)b*SS + q)*SS;
        float* prow = prob + ((size_t)bh*SS + q)*SS;
        #pragma unroll 4
        for (int j = 0; j < 64; j++) {
            int k = j*32 + lane;
            float p = fmaf(srow[k], ip, brow[k]);
            srow[k] = p;
            prow[k] = p;
        }
    }
    __syncthreads();

    // ---------- Phase 3: out = prob @ V (4r x 8d reg tile, 32-way k-split) --
    {
        const int split = tid >> 4;           // 0..31
        const int pos = tid & 15;
        const int rg = (pos & 3) * 4;         // row group base
        const int dg = (pos >> 2) * 8;        // d group base
        unsigned long long acc[4][4];
        #pragma unroll
        for (int i = 0; i < 4; i++)
            #pragma unroll
            for (int j = 0; j < 4; j++) acc[i][j] = 0ull;

        for (int t = 0; t < SS/KT; t++) {
            __syncthreads();
            {
                const float4* src = (const float4*)(g_v + ((size_t)bh*SS + t*KT)*HD);
                #pragma unroll
                for (int r2 = 0; r2 < 2; r2++) {
                    int idx = tid + 512*r2;
                    float4 vv = src[idx];
                    int kk = idx >> 3, oc = (idx & 7) * 4;
                    *(float4*)&KVf[kk*36 + oc] = vv;
                }
            }
            __syncthreads();
            #pragma unroll
            for (int j = 0; j < 4; j++) {
                int kloc = split*4 + j;
                const ulonglong2* vp = (const ulonglong2*)&KVf[kloc*36 + dg];
                ulonglong2 va = vp[0], vb = vp[1];
                int kg = t*KT + kloc;
                #pragma unroll
                for (int rr = 0; rr < 4; rr++) {
                    float p = Ssc[(rg+rr)*SSTR + kg];
                    unsigned long long pp = bcast2(p);
                    ffma2(acc[rr][0], pp, va.x);
                    ffma2(acc[rr][1], pp, va.y);
                    ffma2(acc[rr][2], pp, vb.x);
                    ffma2(acc[rr][3], pp, vb.y);
                }
            }
        }
        __syncthreads();     // all Ssc reads done; reuse as partial buffer
        float* Sp = sm;      // [out][33] partials
        #pragma unroll
        for (int rr = 0; rr < 4; rr++)
            #pragma unroll
            for (int c = 0; c < 4; c++) {
                float2 f = unpack2(acc[rr][c]);
                int o = (rg+rr)*32 + dg + c*2;
                Sp[o*33 + split]     = f.x;
                Sp[(o+1)*33 + split] = f.y;
            }
        __syncthreads();
        {
            int o = tid; // 0..511 = 16 rows x 32 d
            float s = 0.f;
            #pragma unroll
            for (int sp = 0; sp < 32; sp++) s += Sp[o*33 + sp];
            g_o[((size_t)bh*SS + q0 + (o >> 5))*HD + (o & 31)] = s;
        }
    }
}

// ---------------------------------------------------------------------------
// Kernel 5: pred = out @ Wout + bout
// ---------------------------------------------------------------------------
__global__ void pred_kernel(const float* __restrict__ Wout,
                            const float* __restrict__ bout,
                            float* __restrict__ pred)
{
    int t = blockIdx.x;
    int d = threadIdx.x; // 0..127
    int bb = t >> 11, s = t & (SS-1);
    int h = d >> 5, hd = d & 31;
    float v = g_o[(((size_t)(bb*HH + h))*SS + s)*HD + hd] * Wout[d];
    __shared__ float red[4];
    #pragma unroll
    for (int o = 16; o; o >>= 1) v += __shfl_xor_sync(0xffffffffu, v, o);
    if ((d & 31) == 0) red[d >> 5] = v;
    __syncthreads();
    if (d == 0) pred[t] = red[0] + red[1] + red[2] + red[3] + bout[0];
}

// ---------------------------------------------------------------------------
extern "C" void kernel_launch(void* const* d_in, const int* in_sizes, int n_in,
                              void* d_out, int out_size)
{
    const int*   item_in   = (const int*)  d_in[0];
    const int*   skill_in  = (const int*)  d_in[1];
    const int*   label_in  = (const int*)  d_in[2];
    const int*   item_ids  = (const int*)  d_in[3];
    const int*   skill_ids = (const int*)  d_in[4];
    const float* rel       = (const float*)d_in[5];
    const float* ts        = (const float*)d_in[6];
    const float* item_emb  = (const float*)d_in[7];
    const float* skill_emb = (const float*)d_in[8];
    const float* Win       = (const float*)d_in[9];
    const float* b_in      = (const float*)d_in[10];
    const float* Wq        = (const float*)d_in[11];
    const float* bq        = (const float*)d_in[12];
    const float* Wk        = (const float*)d_in[13];
    const float* bk        = (const float*)d_in[14];
    const float* Wv        = (const float*)d_in[15];
    const float* bv        = (const float*)d_in[16];
    const float* Wout      = (const float*)d_in[17];
    const float* bout      = (const float*)d_in[18];
    const float* l1        = (const float*)d_in[19];
    const float* l2        = (const float*)d_in[20];

    float* pred = (float*)d_out;          // [B,S,1] = 8192
    float* prob = pred + NTOK;            // [B,H,S,S]

    cudaFuncSetAttribute(attn_kernel,
                         cudaFuncAttributeMaxDynamicSharedMemorySize,
                         ATTN_SMEM);

    build_kernel<<<NTOK, 128>>>(item_in, skill_in, label_in, item_ids,
                                skill_ids, item_emb, skill_emb);

    base_kernel<<<NTOK, 256>>>(ts, rel, l1, l2);

    // H = relu(X @ Win + b_in)
    sgemm_kernel<<<dim3(4, 128, 1), 256>>>(Win, b_in, Win, b_in, Win, b_in,
                                           512, 256, 0);
    // q,k,v in one launch (z-dispatch)
    sgemm_kernel<<<dim3(2, 128, 3), 256>>>(Wq, bq, Wk, bk, Wv, bv,
                                           256, 128, 1);

    attn_kernel<<<dim3(NBH, SS/TQ), 512, ATTN_SMEM>>>(l1, l2, prob);

    pred_kernel<<<NTOK, 128>>>(Wout, bout, pred);
}

// round 3
// speedup vs baseline: 2.5600x; 1.8307x over previous
#include <cuda_runtime.h>
#include <cuda_bf16.h>
#include <math.h>

// Problem constants
#define BB 4
#define SS 2048
#define EE 128
#define HH 4
#define HD 32
#define NTOK (BB*SS)          // 8192
#define NBH  (BB*HH)          // 16

// Scratch (device globals: allocation-free rule)
__device__ float        g_X[NTOK*512];      // zero-padded RKT input [8192,512]
__device__ float        g_Q256[NTOK*256];   // query concat [8192,256]
__device__ float        g_H[NTOK*256];      // relu(X@Win+b) [8192,256]
__device__ unsigned int g_qb[NBH*SS*16];    // q bf16x2 [B*H,S,16]
__device__ unsigned int g_kb[NBH*SS*16];    // k bf16x2
__device__ float        g_v[NBH*SS*HD];     // v f32 [B*H,S,32]
__device__ float        g_o[NBH*SS*HD];     // attention output
__device__ float        g_base[(size_t)BB*SS*SS]; // c_t*time_attn + c_r*rel_attn

// ---------------------------------------------------------------------------
// f32x2 packed-math helpers
// ---------------------------------------------------------------------------
__device__ __forceinline__ void ffma2(unsigned long long& d,
                                      unsigned long long a, unsigned long long b) {
    asm("fma.rn.f32x2 %0, %1, %2, %0;" : "+l"(d) : "l"(a), "l"(b));
}
__device__ __forceinline__ unsigned long long bcast2(float x) {
    unsigned long long r;
    asm("mov.b64 %0, {%1, %1};" : "=l"(r) : "f"(x));
    return r;
}
__device__ __forceinline__ float2 unpack2(unsigned long long v) {
    float2 f;
    asm("mov.b64 {%0, %1}, %2;" : "=f"(f.x), "=f"(f.y) : "l"(v));
    return f;
}

// ---------------------------------------------------------------------------
// Kernel 1: build X512 and Q256 from embedding gathers
// ---------------------------------------------------------------------------
__global__ void build_kernel(const int* __restrict__ item_in,
                             const int* __restrict__ skill_in,
                             const int* __restrict__ label_in,
                             const int* __restrict__ item_ids,
                             const int* __restrict__ skill_ids,
                             const float* __restrict__ item_emb,
                             const float* __restrict__ skill_emb)
{
    int t = blockIdx.x;
    int d = threadIdx.x; // 0..127
    int lb = label_in[t];
    float itv = item_emb[(size_t)item_in[t]*EE + d];
    float skv = skill_emb[(size_t)skill_in[t]*EE + d];
    float* x = g_X + (size_t)t*512;
    x[d]       = lb ? itv : 0.f;
    x[128 + d] = lb ? 0.f : itv;
    x[256 + d] = lb ? skv : 0.f;
    x[384 + d] = lb ? 0.f : skv;
    float* qx = g_Q256 + (size_t)t*256;
    qx[d]       = item_emb[(size_t)item_ids[t]*EE + d];
    qx[128 + d] = skill_emb[(size_t)skill_ids[t]*EE + d];
}

// ---------------------------------------------------------------------------
// Kernel 2: precompute base = c_t*time_attn + c_r*rel_attn  (head-invariant)
// ---------------------------------------------------------------------------
__global__ __launch_bounds__(256) void base_kernel(const float* __restrict__ ts,
                                                   const float* __restrict__ rel,
                                                   const float* __restrict__ l1p,
                                                   const float* __restrict__ l2p)
{
    __shared__ float et[SS];
    __shared__ float er[SS];
    __shared__ float red[32];

    const int tid = threadIdx.x;
    const int row = blockIdx.x;
    const int q = row & (SS-1);
    const float l1 = *l1p, l2 = *l2p;

    const float* tsrow  = ts  + (size_t)row*SS;
    const float* relrow = rel + (size_t)row*SS;

    float st = 0.f, mr = -1e30f;
    #pragma unroll
    for (int j = 0; j < 8; j++) {
        int k = tid + 256*j;
        float tv = tsrow[k];
        float e1 = (k <= q) ? __expf(__expf(-fabsf(tv))) : 0.f;
        et[k] = e1; st += e1;
        float rv = relrow[k];
        float rr = (k > q && rv != 0.f) ? rv : -10000.f;
        er[k] = rr; mr = fmaxf(mr, rr);
    }
    #pragma unroll
    for (int o = 16; o; o >>= 1) {
        st += __shfl_xor_sync(0xffffffffu, st, o);
        mr  = fmaxf(mr, __shfl_xor_sync(0xffffffffu, mr, o));
    }
    if ((tid & 31) == 0) { red[tid>>5] = st; red[8 + (tid>>5)] = mr; }
    __syncthreads();
    if (tid == 0) {
        float s = 0.f, m = -1e30f;
        #pragma unroll
        for (int i = 0; i < 8; i++) { s += red[i]; m = fmaxf(m, red[8+i]); }
        red[16] = s; red[17] = m;
    }
    __syncthreads();
    st = red[16]; mr = red[17];

    float sr = 0.f;
    #pragma unroll
    for (int j = 0; j < 8; j++) {
        int k = tid + 256*j;
        float e = __expf(er[k] - mr);
        er[k] = e; sr += e;
    }
    #pragma unroll
    for (int o = 16; o; o >>= 1) sr += __shfl_xor_sync(0xffffffffu, sr, o);
    if ((tid & 31) == 0) red[tid>>5] = sr;
    __syncthreads();
    if (tid == 0) {
        float s = 0.f;
        #pragma unroll
        for (int i = 0; i < 8; i++) s += red[i];
        red[18] = s;
    }
    __syncthreads();
    sr = red[18];

    const float ct = (1.f - l1) * l2 / st;
    const float cr = l1 / sr;
    float* brow = g_base + (size_t)row*SS;
    #pragma unroll
    for (int j = 0; j < 8; j++) {
        int k = tid + 256*j;
        brow[k] = fmaf(ct, et[k], cr * er[k]);
    }
}

// ---------------------------------------------------------------------------
// Kernel 3: tiled SGEMM with z-dispatch over up to 3 weight sets.
// ---------------------------------------------------------------------------
__global__ __launch_bounds__(256) void sgemm_kernel(
    const float* __restrict__ W0, const float* __restrict__ B0,
    const float* __restrict__ W1, const float* __restrict__ B1,
    const float* __restrict__ W2, const float* __restrict__ B2,
    int K, int N, int obase)
{
    __shared__ float As[16*68];
    __shared__ float Ws[16*64];

    const int z = blockIdx.z;
    const float* W    = (z == 0) ? W0 : (z == 1) ? W1 : W2;
    const float* bias = (z == 0) ? B0 : (z == 1) ? B1 : B2;
    const int osel = obase + z;
    const float* A = (osel == 0) ? g_X : (osel == 1) ? g_Q256 : g_H;

    int tid = threadIdx.x;
    int bx = blockIdx.x, by = blockIdx.y;
    int tx = tid & 15, ty = tid >> 4;

    float acc[4][4];
    #pragma unroll
    for (int i = 0; i < 4; i++)
        #pragma unroll
        for (int j = 0; j < 4; j++) acc[i][j] = 0.f;

    int arow  = tid >> 2;
    int acol4 = (tid & 3) * 4;
    int wrow  = tid >> 4;
    int wcol4 = (tid & 15) * 4;

    const float* Aptr = A + ((size_t)(by*64 + arow))*K + acol4;
    const float* Wptr = W + (size_t)wrow*N + bx*64 + wcol4;

    for (int kk = 0; kk < K; kk += 16) {
        float4 av = *(const float4*)(Aptr + kk);
        float4 wv = *(const float4*)(Wptr + (size_t)kk*N);
        __syncthreads();
        As[(acol4+0)*68 + arow] = av.x;
        As[(acol4+1)*68 + arow] = av.y;
        As[(acol4+2)*68 + arow] = av.z;
        As[(acol4+3)*68 + arow] = av.w;
        *(float4*)&Ws[wrow*64 + wcol4] = wv;
        __syncthreads();
        #pragma unroll
        for (int k = 0; k < 16; k++) {
            float4 a = *(const float4*)&As[k*68 + ty*4];
            float4 bq = *(const float4*)&Ws[k*64 + tx*4];
            float ar[4] = {a.x, a.y, a.z, a.w};
            float br[4] = {bq.x, bq.y, bq.z, bq.w};
            #pragma unroll
            for (int i = 0; i < 4; i++)
                #pragma unroll
                for (int j = 0; j < 4; j++)
                    acc[i][j] += ar[i] * br[j];
        }
    }

    int m0 = by*64 + ty*4, n0 = bx*64 + tx*4;
    if (osel == 0) {
        #pragma unroll
        for (int i = 0; i < 4; i++)
            #pragma unroll
            for (int j = 0; j < 4; j++)
                g_H[(size_t)(m0+i)*256 + n0 + j] = fmaxf(acc[i][j] + bias[n0+j], 0.f);
    } else if (osel == 3) {
        #pragma unroll
        for (int i = 0; i < 4; i++) {
            int m = m0 + i, bb = m >> 11, s = m & (SS-1);
            int h = n0 >> 5, hd = n0 & 31;
            float* o = g_v + (((size_t)(bb*HH + h))*SS + s)*HD + hd;
            #pragma unroll
            for (int j = 0; j < 4; j++) o[j] = acc[i][j] + bias[n0+j];
        }
    } else {
        unsigned int* dstbase = (osel == 1) ? g_qb : g_kb;
        #pragma unroll
        for (int i = 0; i < 4; i++) {
            int m = m0 + i, bb = m >> 11, s = m & (SS-1);
            int h = n0 >> 5, hd = n0 & 31;
            float v0 = acc[i][0] + bias[n0+0];
            float v1 = acc[i][1] + bias[n0+1];
            float v2 = acc[i][2] + bias[n0+2];
            float v3 = acc[i][3] + bias[n0+3];
            __nv_bfloat162 p0 = __floats2bfloat162_rn(v0, v1);
            __nv_bfloat162 p1 = __floats2bfloat162_rn(v2, v3);
            unsigned int* dst = dstbase + (((size_t)(bb*HH + h))*SS + s)*16 + (hd >> 1);
            dst[0] = reinterpret_cast<unsigned int&>(p0);
            dst[1] = reinterpret_cast<unsigned int&>(p1);
        }
    }
}

// ---------------------------------------------------------------------------
// Kernel 4: fused attention. grid = (16 bh, 256 qtiles), 512 threads, TQ=8.
// 2 CTAs/SM (smem 84.5KB, regs capped at 64). Causal skip above kcut.
// ---------------------------------------------------------------------------
#define TQ 8
#define KT 128
#define SSTR 2064
#define ATTN_SMEM ((TQ*SSTR + KT*36 + 32)*4)

__global__ __launch_bounds__(512, 2) void attn_kernel(
    const float* __restrict__ l1p, const float* __restrict__ l2p,
    float* __restrict__ prob)
{
    extern __shared__ float sm[];
    float* Ssc = sm;                     // TQ x SSTR
    float* KVf = sm + TQ*SSTR;           // 128 x 36
    float* Red = KVf + KT*36;            // 32
    unsigned int* KVu = (unsigned int*)KVf;

    const int tid = threadIdx.x;
    const int bh = blockIdx.x;
    const int q0 = (gridDim.y - 1 - blockIdx.y) * TQ;  // heavy blocks first
    const int b  = bh >> 2;
    const int w = tid >> 5, lane = tid & 31;
    const int row = w & 7, half = w >> 3;

    const int ktiles = (q0 + TQ + KT - 1) / KT;  // causal cut (tiles of 128)

    // ---------- Phase 1: scores = (q@k^T)/sqrt(HD), bf16 HFMA2 ----------
    {
        const int qg = q0 + row;
        unsigned int qu[16];
        const uint4* qp = (const uint4*)(g_qb + ((size_t)bh*SS + qg)*16);
        #pragma unroll
        for (int i = 0; i < 4; i++) {
            uint4 t0 = qp[i];
            qu[4*i+0]=t0.x; qu[4*i+1]=t0.y; qu[4*i+2]=t0.z; qu[4*i+3]=t0.w;
        }
        const __nv_bfloat162* qh = (const __nv_bfloat162*)qu;
        const float scale = 0.17677669529663687f;

        for (int t = 0; t < ktiles; t++) {
            __syncthreads();
            {
                const uint4* src = (const uint4*)(g_kb + ((size_t)bh*SS + t*KT)*16);
                uint4 vk = src[tid];
                int kk = tid >> 2, qd = (tid & 3) * 4;
                *(uint4*)&KVu[kk*20 + qd] = vk;
            }
            __syncthreads();
            #pragma unroll
            for (int j = 0; j < 2; j++) {
                int kloc = half*64 + j*32 + lane;
                const uint4* kp = (const uint4*)&KVu[kloc*20];
                uint4 ka = kp[0], kb4 = kp[1], kc = kp[2], kd = kp[3];
                unsigned int kvu[16] = {ka.x,ka.y,ka.z,ka.w, kb4.x,kb4.y,kb4.z,kb4.w,
                                        kc.x,kc.y,kc.z,kc.w, kd.x,kd.y,kd.z,kd.w};
                const __nv_bfloat162* kh = (const __nv_bfloat162*)kvu;
                __nv_bfloat162 a0 = __floats2bfloat162_rn(0.f, 0.f);
                #pragma unroll
                for (int i = 0; i < 16; i++) a0 = __hfma2(qh[i], kh[i], a0);
                float2 f0 = __bfloat1622float2(a0);
                int kg = t*KT + kloc;
                float s0 = (f0.x + f0.y) * scale;
                Ssc[row*SSTR + kg] = (kg > qg) ? -1e9f : s0;
            }
        }
    }
    __syncthreads();

    // ---------- Phase 2: QK softmax + mix with precomputed base ----------
    {
        const float l1 = *l1p, l2 = *l2p;
        const float cp = (1.f - l1) * (1.f - l2);
        const int q = q0 + row;           // 2 warps per row (half 0/1)
        float* srow = Ssc + row*SSTR;
        const float4* brow4 = (const float4*)(g_base + ((size_t)b*SS + q)*SS);
        float4* prow4 = (float4*)(prob + ((size_t)bh*SS + q)*SS);

        float zs = 0.f;
        #pragma unroll
        for (int jj = 0; jj < 8; jj++) {
            int j = half*8 + jj;          // each j = 128 floats = one k-tile
            if (j < ktiles) {
                int k4 = j*32 + lane;
                float4 s = *(float4*)&srow[4*k4];
                s.x = __expf(s.x); s.y = __expf(s.y);
                s.z = __expf(s.z); s.w = __expf(s.w);
                zs += (s.x + s.y) + (s.z + s.w);
                *(float4*)&srow[4*k4] = s;
            }
        }
        #pragma unroll
        for (int o = 16; o; o >>= 1) zs += __shfl_xor_sync(0xffffffffu, zs, o);
        if (lane == 0) Red[row*2 + half] = zs;
        __syncthreads();
        const float ip = cp / (Red[row*2] + Red[row*2+1]);

        #pragma unroll
        for (int jj = 0; jj < 8; jj++) {
            int j = half*8 + jj;
            int k4 = j*32 + lane;
            float4 bv = brow4[k4];
            float4 p;
            if (j < ktiles) {
                float4 e = *(float4*)&srow[4*k4];
                p.x = fmaf(e.x, ip, bv.x);
                p.y = fmaf(e.y, ip, bv.y);
                p.z = fmaf(e.z, ip, bv.z);
                p.w = fmaf(e.w, ip, bv.w);
            } else {
                p = bv;                    // masked region: prob = base
            }
            *(float4*)&srow[4*k4] = p;
            prow4[k4] = p;
        }
    }
    __syncthreads();

    // ---------- Phase 3: out = prob @ V (4r x 4d reg tile, 32-way k-split) --
    {
        const int split = tid >> 4;            // 0..31
        const int pos = tid & 15;
        const int rg = (pos & 1) * 4;          // row group: 0 or 4
        const int dg8 = pos >> 1;              // d group: 0..7 (x4 floats)
        unsigned long long acc[4][2];
        #pragma unroll
        for (int i = 0; i < 4; i++) { acc[i][0] = 0ull; acc[i][1] = 0ull; }

        for (int t = 0; t < SS/KT; t++) {
            __syncthreads();
            {
                const float4* src = (const float4*)(g_v + ((size_t)bh*SS + t*KT)*HD);
                #pragma unroll
                for (int r2 = 0; r2 < 2; r2++) {
                    int idx = tid + 512*r2;
                    float4 vv = src[idx];
                    int kk = idx >> 3, oc = (idx & 7) * 4;
                    *(float4*)&KVf[kk*36 + oc] = vv;
                }
            }
            __syncthreads();
            #pragma unroll
            for (int j = 0; j < 4; j++) {
                int kloc = split*4 + j;
                ulonglong2 vv = *(const ulonglong2*)&KVf[kloc*36 + dg8*4];
                int kg = t*KT + kloc;
                #pragma unroll
                for (int rr = 0; rr < 4; rr++) {
                    float p = Ssc[(rg+rr)*SSTR + kg];
                    unsigned long long pp = bcast2(p);
                    ffma2(acc[rr][0], pp, vv.x);
                    ffma2(acc[rr][1], pp, vv.y);
                }
            }
        }
        __syncthreads();     // Ssc reads done; reuse as partial buffer
        float* Sp = sm;      // [256 outputs][33] partials
        #pragma unroll
        for (int rr = 0; rr < 4; rr++)
            #pragma unroll
            for (int c = 0; c < 2; c++) {
                float2 f = unpack2(acc[rr][c]);
                int o = (rg+rr)*32 + dg8*4 + c*2;
                Sp[o*33 + split]     = f.x;
                Sp[(o+1)*33 + split] = f.y;
            }
        __syncthreads();
        if (tid < 256) {
            int o = tid; // 8 rows x 32 d
            float s = 0.f;
            #pragma unroll
            for (int sp = 0; sp < 32; sp++) s += Sp[o*33 + sp];
            g_o[((size_t)bh*SS + q0 + (o >> 5))*HD + (o & 31)] = s;
        }
    }
}

// ---------------------------------------------------------------------------
// Kernel 5: pred = out @ Wout + bout
// ---------------------------------------------------------------------------
__global__ void pred_kernel(const float* __restrict__ Wout,
                            const float* __restrict__ bout,
                            float* __restrict__ pred)
{
    int t = blockIdx.x;
    int d = threadIdx.x; // 0..127
    int bb = t >> 11, s = t & (SS-1);
    int h = d >> 5, hd = d & 31;
    float v = g_o[(((size_t)(bb*HH + h))*SS + s)*HD + hd] * Wout[d];
    __shared__ float red[4];
    #pragma unroll
    for (int o = 16; o; o >>= 1) v += __shfl_xor_sync(0xffffffffu, v, o);
    if ((d & 31) == 0) red[d >> 5] = v;
    __syncthreads();
    if (d == 0) pred[t] = red[0] + red[1] + red[2] + red[3] + bout[0];
}

// ---------------------------------------------------------------------------
extern "C" void kernel_launch(void* const* d_in, const int* in_sizes, int n_in,
                              void* d_out, int out_size)
{
    const int*   item_in   = (const int*)  d_in[0];
    const int*   skill_in  = (const int*)  d_in[1];
    const int*   label_in  = (const int*)  d_in[2];
    const int*   item_ids  = (const int*)  d_in[3];
    const int*   skill_ids = (const int*)  d_in[4];
    const float* rel       = (const float*)d_in[5];
    const float* ts        = (const float*)d_in[6];
    const float* item_emb  = (const float*)d_in[7];
    const float* skill_emb = (const float*)d_in[8];
    const float* Win       = (const float*)d_in[9];
    const float* b_in      = (const float*)d_in[10];
    const float* Wq        = (const float*)d_in[11];
    const float* bq        = (const float*)d_in[12];
    const float* Wk        = (const float*)d_in[13];
    const float* bk        = (const float*)d_in[14];
    const float* Wv        = (const float*)d_in[15];
    const float* bv        = (const float*)d_in[16];
    const float* Wout      = (const float*)d_in[17];
    const float* bout      = (const float*)d_in[18];
    const float* l1        = (const float*)d_in[19];
    const float* l2        = (const float*)d_in[20];

    float* pred = (float*)d_out;          // [B,S,1] = 8192
    float* prob = pred + NTOK;            // [B,H,S,S]

    cudaFuncSetAttribute(attn_kernel,
                         cudaFuncAttributeMaxDynamicSharedMemorySize,
                         ATTN_SMEM);

    build_kernel<<<NTOK, 128>>>(item_in, skill_in, label_in, item_ids,
                                skill_ids, item_emb, skill_emb);

    base_kernel<<<NTOK, 256>>>(ts, rel, l1, l2);

    // H = relu(X @ Win + b_in)
    sgemm_kernel<<<dim3(4, 128, 1), 256>>>(Win, b_in, Win, b_in, Win, b_in,
                                           512, 256, 0);
    // q,k,v in one launch (z-dispatch)
    sgemm_kernel<<<dim3(2, 128, 3), 256>>>(Wq, bq, Wk, bk, Wv, bv,
                                           256, 128, 1);

    attn_kernel<<<dim3(NBH, SS/TQ), 512, ATTN_SMEM>>>(l1, l2, prob);

    pred_kernel<<<NTOK, 128>>>(Wout, bout, pred);
}

// round 4
// speedup vs baseline: 2.9782x; 1.1634x over previous
#include <cuda_runtime.h>
#include <cuda_bf16.h>
#include <math.h>

// Problem constants
#define BB 4
#define SS 2048
#define EE 128
#define HH 4
#define HD 32
#define NTOK (BB*SS)          // 8192
#define NBH  (BB*HH)          // 16

// Scratch (device globals: allocation-free rule)
__device__ float        g_X[NTOK*512];
__device__ float        g_Q256[NTOK*256];
__device__ float        g_H[NTOK*256];
__device__ unsigned int g_qb[NBH*SS*16];    // q bf16x2 [B*H,S,16]
__device__ unsigned int g_kb[NBH*SS*16];    // k bf16x2
__device__ float        g_v[NBH*SS*HD];     // v f32 [B*H,S,32]
__device__ float        g_o[NBH*SS*HD];     // attention output
__device__ float        g_base[(size_t)BB*SS*SS];

// ---------------------------------------------------------------------------
__device__ __forceinline__ unsigned int f2tf32(float x) {
    unsigned int r;
    asm("cvt.rna.tf32.f32 %0, %1;" : "=r"(r) : "f"(x));
    return r;
}

// ---------------------------------------------------------------------------
// Kernel 1: build X512 and Q256 from embedding gathers
// ---------------------------------------------------------------------------
__global__ void build_kernel(const int* __restrict__ item_in,
                             const int* __restrict__ skill_in,
                             const int* __restrict__ label_in,
                             const int* __restrict__ item_ids,
                             const int* __restrict__ skill_ids,
                             const float* __restrict__ item_emb,
                             const float* __restrict__ skill_emb)
{
    int t = blockIdx.x;
    int d = threadIdx.x; // 0..127
    int lb = label_in[t];
    float itv = item_emb[(size_t)item_in[t]*EE + d];
    float skv = skill_emb[(size_t)skill_in[t]*EE + d];
    float* x = g_X + (size_t)t*512;
    x[d]       = lb ? itv : 0.f;
    x[128 + d] = lb ? 0.f : itv;
    x[256 + d] = lb ? skv : 0.f;
    x[384 + d] = lb ? 0.f : skv;
    float* qx = g_Q256 + (size_t)t*256;
    qx[d]       = item_emb[(size_t)item_ids[t]*EE + d];
    qx[128 + d] = skill_emb[(size_t)skill_ids[t]*EE + d];
}

// ---------------------------------------------------------------------------
// Kernel 2: precompute base = c_t*time_attn + c_r*rel_attn  (head-invariant)
// ---------------------------------------------------------------------------
__global__ __launch_bounds__(256) void base_kernel(const float* __restrict__ ts,
                                                   const float* __restrict__ rel,
                                                   const float* __restrict__ l1p,
                                                   const float* __restrict__ l2p)
{
    __shared__ float et[SS];
    __shared__ float er[SS];
    __shared__ float red[32];

    const int tid = threadIdx.x;
    const int row = blockIdx.x;
    const int q = row & (SS-1);
    const float l1 = *l1p, l2 = *l2p;

    const float* tsrow  = ts  + (size_t)row*SS;
    const float* relrow = rel + (size_t)row*SS;

    float st = 0.f, mr = -1e30f;
    #pragma unroll
    for (int j = 0; j < 8; j++) {
        int k = tid + 256*j;
        float tv = tsrow[k];
        float e1 = (k <= q) ? __expf(__expf(-fabsf(tv))) : 0.f;
        et[k] = e1; st += e1;
        float rv = relrow[k];
        float rr = (k > q && rv != 0.f) ? rv : -10000.f;
        er[k] = rr; mr = fmaxf(mr, rr);
    }
    #pragma unroll
    for (int o = 16; o; o >>= 1) {
        st += __shfl_xor_sync(0xffffffffu, st, o);
        mr  = fmaxf(mr, __shfl_xor_sync(0xffffffffu, mr, o));
    }
    if ((tid & 31) == 0) { red[tid>>5] = st; red[8 + (tid>>5)] = mr; }
    __syncthreads();
    if (tid == 0) {
        float s = 0.f, m = -1e30f;
        #pragma unroll
        for (int i = 0; i < 8; i++) { s += red[i]; m = fmaxf(m, red[8+i]); }
        red[16] = s; red[17] = m;
    }
    __syncthreads();
    st = red[16]; mr = red[17];

    float sr = 0.f;
    #pragma unroll
    for (int j = 0; j < 8; j++) {
        int k = tid + 256*j;
        float e = __expf(er[k] - mr);
        er[k] = e; sr += e;
    }
    #pragma unroll
    for (int o = 16; o; o >>= 1) sr += __shfl_xor_sync(0xffffffffu, sr, o);
    if ((tid & 31) == 0) red[tid>>5] = sr;
    __syncthreads();
    if (tid == 0) {
        float s = 0.f;
        #pragma unroll
        for (int i = 0; i < 8; i++) s += red[i];
        red[18] = s;
    }
    __syncthreads();
    sr = red[18];

    const float ct = (1.f - l1) * l2 / st;
    const float cr = l1 / sr;
    float* brow = g_base + (size_t)row*SS;
    #pragma unroll
    for (int j = 0; j < 8; j++) {
        int k = tid + 256*j;
        brow[k] = fmaf(ct, et[k], cr * er[k]);
    }
}

// ---------------------------------------------------------------------------
// Kernel 3: tiled SGEMM with z-dispatch over up to 3 weight sets.
// ---------------------------------------------------------------------------
__global__ __launch_bounds__(256) void sgemm_kernel(
    const float* __restrict__ W0, const float* __restrict__ B0,
    const float* __restrict__ W1, const float* __restrict__ B1,
    const float* __restrict__ W2, const float* __restrict__ B2,
    int K, int N, int obase)
{
    __shared__ float As[16*68];
    __shared__ float Ws[16*64];

    const int z = blockIdx.z;
    const float* W    = (z == 0) ? W0 : (z == 1) ? W1 : W2;
    const float* bias = (z == 0) ? B0 : (z == 1) ? B1 : B2;
    const int osel = obase + z;
    const float* A = (osel == 0) ? g_X : (osel == 1) ? g_Q256 : g_H;

    int tid = threadIdx.x;
    int bx = blockIdx.x, by = blockIdx.y;
    int tx = tid & 15, ty = tid >> 4;

    float acc[4][4];
    #pragma unroll
    for (int i = 0; i < 4; i++)
        #pragma unroll
        for (int j = 0; j < 4; j++) acc[i][j] = 0.f;

    int arow  = tid >> 2;
    int acol4 = (tid & 3) * 4;
    int wrow  = tid >> 4;
    int wcol4 = (tid & 15) * 4;

    const float* Aptr = A + ((size_t)(by*64 + arow))*K + acol4;
    const float* Wptr = W + (size_t)wrow*N + bx*64 + wcol4;

    for (int kk = 0; kk < K; kk += 16) {
        float4 av = *(const float4*)(Aptr + kk);
        float4 wv = *(const float4*)(Wptr + (size_t)kk*N);
        __syncthreads();
        As[(acol4+0)*68 + arow] = av.x;
        As[(acol4+1)*68 + arow] = av.y;
        As[(acol4+2)*68 + arow] = av.z;
        As[(acol4+3)*68 + arow] = av.w;
        *(float4*)&Ws[wrow*64 + wcol4] = wv;
        __syncthreads();
        #pragma unroll
        for (int k = 0; k < 16; k++) {
            float4 a = *(const float4*)&As[k*68 + ty*4];
            float4 bq = *(const float4*)&Ws[k*64 + tx*4];
            float ar[4] = {a.x, a.y, a.z, a.w};
            float br[4] = {bq.x, bq.y, bq.z, bq.w};
            #pragma unroll
            for (int i = 0; i < 4; i++)
                #pragma unroll
                for (int j = 0; j < 4; j++)
                    acc[i][j] += ar[i] * br[j];
        }
    }

    int m0 = by*64 + ty*4, n0 = bx*64 + tx*4;
    if (osel == 0) {
        #pragma unroll
        for (int i = 0; i < 4; i++)
            #pragma unroll
            for (int j = 0; j < 4; j++)
                g_H[(size_t)(m0+i)*256 + n0 + j] = fmaxf(acc[i][j] + bias[n0+j], 0.f);
    } else if (osel == 3) {
        #pragma unroll
        for (int i = 0; i < 4; i++) {
            int m = m0 + i, bb = m >> 11, s = m & (SS-1);
            int h = n0 >> 5, hd = n0 & 31;
            float* o = g_v + (((size_t)(bb*HH + h))*SS + s)*HD + hd;
            #pragma unroll
            for (int j = 0; j < 4; j++) o[j] = acc[i][j] + bias[n0+j];
        }
    } else {
        unsigned int* dstbase = (osel == 1) ? g_qb : g_kb;
        #pragma unroll
        for (int i = 0; i < 4; i++) {
            int m = m0 + i, bb = m >> 11, s = m & (SS-1);
            int h = n0 >> 5, hd = n0 & 31;
            float v0 = acc[i][0] + bias[n0+0];
            float v1 = acc[i][1] + bias[n0+1];
            float v2 = acc[i][2] + bias[n0+2];
            float v3 = acc[i][3] + bias[n0+3];
            __nv_bfloat162 p0 = __floats2bfloat162_rn(v0, v1);
            __nv_bfloat162 p1 = __floats2bfloat162_rn(v2, v3);
            unsigned int* dst = dstbase + (((size_t)(bb*HH + h))*SS + s)*16 + (hd >> 1);
            dst[0] = reinterpret_cast<unsigned int&>(p0);
            dst[1] = reinterpret_cast<unsigned int&>(p1);
        }
    }
}

// ---------------------------------------------------------------------------
// Kernel 4: QK + softmax + mix -> prob. Warp-per-row, exps in registers.
// grid = (16 bh, 512 qtiles), 256 threads, TQ=4 rows, 2 warps per row
// (halves h=0/1 split each 128-k tile: h covers m = 2h, 2h+1).
// ---------------------------------------------------------------------------
#define TQ 4

__global__ __launch_bounds__(256, 2) void attn_qk_kernel(
    const float* __restrict__ l1p, const float* __restrict__ l2p,
    float* __restrict__ prob)
{
    __shared__ unsigned int KV[128*20];   // k tile, bf16x2, stride 20
    __shared__ float Red[8];

    const int tid = threadIdx.x;
    const int bh = blockIdx.x;
    const int q0 = (gridDim.y - 1 - blockIdx.y) * TQ;  // heavy blocks first
    const int b  = bh >> 2;
    const int w = tid >> 5, lane = tid & 31;
    const int row = w & 3, h = w >> 2;
    const int q = q0 + row;

    const int ktiles = (q0 + TQ + 127) >> 7;
    const float scale = 0.17677669529663687f; // 1/sqrt(32)

    // q row in registers (bf16x2)
    unsigned int qu[16];
    {
        const uint4* qp = (const uint4*)(g_qb + ((size_t)bh*SS + q)*16);
        #pragma unroll
        for (int i = 0; i < 4; i++) {
            uint4 t0 = qp[i];
            qu[4*i+0]=t0.x; qu[4*i+1]=t0.y; qu[4*i+2]=t0.z; qu[4*i+3]=t0.w;
        }
    }
    const __nv_bfloat162* qh = (const __nv_bfloat162*)qu;

    float e[32];            // exp values, 2 k-chunks per tile per warp
    float Zs = 0.f;

    // prefetch first tile
    uint4 pr0, pr1;
    {
        const uint4* src = (const uint4*)(g_kb + ((size_t)bh*SS)*16);
        pr0 = src[tid]; pr1 = src[tid + 256];
    }

    #pragma unroll
    for (int t = 0; t < 16; t++) {
        if (t < ktiles) {
            __syncthreads();
            {
                int i0 = tid,      k0 = i0 >> 2, d0 = (i0 & 3)*4;
                int i1 = tid+256,  k1 = i1 >> 2, d1 = (i1 & 3)*4;
                *(uint4*)&KV[k0*20 + d0] = pr0;
                *(uint4*)&KV[k1*20 + d1] = pr1;
            }
            __syncthreads();
            if (t + 1 < ktiles) {
                const uint4* src = (const uint4*)(g_kb + ((size_t)bh*SS + (t+1)*128)*16);
                pr0 = src[tid]; pr1 = src[tid + 256];
            }
            #pragma unroll
            for (int mm = 0; mm < 2; mm++) {
                int m = 2*h + mm;
                int kloc = m*32 + lane;
                const uint4* kp = (const uint4*)&KV[kloc*20];
                uint4 ka = kp[0], kb4 = kp[1], kc = kp[2], kd = kp[3];
                unsigned int kvu[16] = {ka.x,ka.y,ka.z,ka.w, kb4.x,kb4.y,kb4.z,kb4.w,
                                        kc.x,kc.y,kc.z,kc.w, kd.x,kd.y,kd.z,kd.w};
                const __nv_bfloat162* kh = (const __nv_bfloat162*)kvu;
                __nv_bfloat162 a0 = __floats2bfloat162_rn(0.f, 0.f);
                #pragma unroll
                for (int i = 0; i < 16; i++) a0 = __hfma2(qh[i], kh[i], a0);
                float2 f0 = __bfloat1622float2(a0);
                int kg = t*128 + kloc;
                float s = (f0.x + f0.y) * scale;
                float ev = (kg > q) ? 0.f : __expf(s);
                e[t*2 + mm] = ev;
                Zs += ev;
            }
        }
    }

    // row sum across the two half-warps
    #pragma unroll
    for (int o = 16; o; o >>= 1) Zs += __shfl_xor_sync(0xffffffffu, Zs, o);
    if (lane == 0) Red[row*2 + h] = Zs;
    __syncthreads();
    const float l1 = *l1p, l2 = *l2p;
    const float cp = (1.f - l1) * (1.f - l2);
    const float ip = cp / (Red[row*2] + Red[row*2 + 1]);

    const float* brow = g_base + ((size_t)b*SS + q)*SS;
    float* prow = prob + ((size_t)bh*SS + q)*SS;
    #pragma unroll
    for (int t = 0; t < 16; t++) {
        #pragma unroll
        for (int mm = 0; mm < 2; mm++) {
            int k = t*128 + (2*h + mm)*32 + lane;
            float bsv = __ldg(brow + k);
            float p = (t < ktiles) ? fmaf(e[t*2 + mm], ip, bsv) : bsv;
            prow[k] = p;
        }
    }
}

// ---------------------------------------------------------------------------
// Kernel 5: PV GEMM via tf32 mma.sync: out[bh] = prob[bh] @ V[bh]
// grid = (32 qtiles, 16 bh), 256 threads (8 warps). 64q x 32d tile, k chunks of 64.
// Warp w: q rows (w&3)*16.., n cols (w>>2)*16.. (2 n8-tiles).
// ---------------------------------------------------------------------------
__global__ __launch_bounds__(256) void pv_kernel(const float* __restrict__ prob)
{
    __shared__ unsigned int Ps[64*68];   // prob tile (tf32), stride 68
    __shared__ unsigned int Vs[64*40];   // V tile (tf32),   stride 40

    const int tid = threadIdx.x;
    const int w = tid >> 5, lane = tid & 31;
    const int g = lane >> 2, t4 = lane & 3;
    const int q0 = blockIdx.x * 64;
    const int bh = blockIdx.y;
    const int qsub = (w & 3) * 16;
    const int nsub = (w >> 2) * 16;

    const float* Pg = prob + ((size_t)bh*SS + q0)*SS;
    const float* Vg = g_v + (size_t)bh*SS*HD;

    float c0[2][4];
    #pragma unroll
    for (int nt = 0; nt < 2; nt++)
        #pragma unroll
        for (int i = 0; i < 4; i++) c0[nt][i] = 0.f;

    float4 pr[4];
    float4 vr[2];
    // prefetch chunk 0
    #pragma unroll
    for (int i = 0; i < 4; i++) {
        int fi = tid + 256*i, r = fi >> 4, cc = (fi & 15)*4;
        pr[i] = *(const float4*)(Pg + (size_t)r*SS + cc);
    }
    #pragma unroll
    for (int i = 0; i < 2; i++) {
        int fi = tid + 256*i, r = fi >> 3, cc = (fi & 7)*4;
        vr[i] = *(const float4*)(Vg + (size_t)r*HD + cc);
    }

    for (int ch = 0; ch < 32; ch++) {
        __syncthreads();
        #pragma unroll
        for (int i = 0; i < 4; i++) {
            int fi = tid + 256*i, r = fi >> 4, cc = (fi & 15)*4;
            uint4 cv = { f2tf32(pr[i].x), f2tf32(pr[i].y),
                         f2tf32(pr[i].z), f2tf32(pr[i].w) };
            *(uint4*)&Ps[r*68 + cc] = cv;
        }
        #pragma unroll
        for (int i = 0; i < 2; i++) {
            int fi = tid + 256*i, r = fi >> 3, cc = (fi & 7)*4;
            uint4 cv = { f2tf32(vr[i].x), f2tf32(vr[i].y),
                         f2tf32(vr[i].z), f2tf32(vr[i].w) };
            *(uint4*)&Vs[r*40 + cc] = cv;
        }
        __syncthreads();
        if (ch < 31) {
            int kc = (ch + 1) * 64;
            #pragma unroll
            for (int i = 0; i < 4; i++) {
                int fi = tid + 256*i, r = fi >> 4, cc = (fi & 15)*4;
                pr[i] = *(const float4*)(Pg + (size_t)r*SS + kc + cc);
            }
            #pragma unroll
            for (int i = 0; i < 2; i++) {
                int fi = tid + 256*i, r = fi >> 3, cc = (fi & 7)*4;
                vr[i] = *(const float4*)(Vg + (size_t)(kc + r)*HD + cc);
            }
        }
        #pragma unroll
        for (int kk = 0; kk < 64; kk += 8) {
            unsigned int a0 = Ps[(qsub + g)*68 + kk + t4];
            unsigned int a1 = Ps[(qsub + g + 8)*68 + kk + t4];
            unsigned int a2 = Ps[(qsub + g)*68 + kk + t4 + 4];
            unsigned int a3 = Ps[(qsub + g + 8)*68 + kk + t4 + 4];
            #pragma unroll
            for (int nt = 0; nt < 2; nt++) {
                unsigned int b0 = Vs[(kk + t4)*40 + nsub + nt*8 + g];
                unsigned int b1 = Vs[(kk + t4 + 4)*40 + nsub + nt*8 + g];
                asm volatile(
                    "mma.sync.aligned.m16n8k8.row.col.f32.tf32.tf32.f32 "
                    "{%0,%1,%2,%3}, {%4,%5,%6,%7}, {%8,%9}, {%0,%1,%2,%3};"
                    : "+f"(c0[nt][0]), "+f"(c0[nt][1]),
                      "+f"(c0[nt][2]), "+f"(c0[nt][3])
                    : "r"(a0), "r"(a1), "r"(a2), "r"(a3), "r"(b0), "r"(b1));
            }
        }
    }

    // epilogue: write g_o
    const int orow = q0 + qsub + g;
    #pragma unroll
    for (int nt = 0; nt < 2; nt++) {
        int col = nsub + nt*8 + 2*t4;
        float2 lo = { c0[nt][0], c0[nt][1] };
        float2 hi = { c0[nt][2], c0[nt][3] };
        *(float2*)&g_o[((size_t)bh*SS + orow)*HD + col]     = lo;
        *(float2*)&g_o[((size_t)bh*SS + orow + 8)*HD + col] = hi;
    }
}

// ---------------------------------------------------------------------------
// Kernel 6: pred = out @ Wout + bout
// ---------------------------------------------------------------------------
__global__ void pred_kernel(const float* __restrict__ Wout,
                            const float* __restrict__ bout,
                            float* __restrict__ pred)
{
    int t = blockIdx.x;
    int d = threadIdx.x; // 0..127
    int bb = t >> 11, s = t & (SS-1);
    int h = d >> 5, hd = d & 31;
    float v = g_o[(((size_t)(bb*HH + h))*SS + s)*HD + hd] * Wout[d];
    __shared__ float red[4];
    #pragma unroll
    for (int o = 16; o; o >>= 1) v += __shfl_xor_sync(0xffffffffu, v, o);
    if ((d & 31) == 0) red[d >> 5] = v;
    __syncthreads();
    if (d == 0) pred[t] = red[0] + red[1] + red[2] + red[3] + bout[0];
}

// ---------------------------------------------------------------------------
extern "C" void kernel_launch(void* const* d_in, const int* in_sizes, int n_in,
                              void* d_out, int out_size)
{
    const int*   item_in   = (const int*)  d_in[0];
    const int*   skill_in  = (const int*)  d_in[1];
    const int*   label_in  = (const int*)  d_in[2];
    const int*   item_ids  = (const int*)  d_in[3];
    const int*   skill_ids = (const int*)  d_in[4];
    const float* rel       = (const float*)d_in[5];
    const float* ts        = (const float*)d_in[6];
    const float* item_emb  = (const float*)d_in[7];
    const float* skill_emb = (const float*)d_in[8];
    const float* Win       = (const float*)d_in[9];
    const float* b_in      = (const float*)d_in[10];
    const float* Wq        = (const float*)d_in[11];
    const float* bq        = (const float*)d_in[12];
    const float* Wk        = (const float*)d_in[13];
    const float* bk        = (const float*)d_in[14];
    const float* Wv        = (const float*)d_in[15];
    const float* bv        = (const float*)d_in[16];
    const float* Wout      = (const float*)d_in[17];
    const float* bout      = (const float*)d_in[18];
    const float* l1        = (const float*)d_in[19];
    const float* l2        = (const float*)d_in[20];

    float* pred = (float*)d_out;          // [B,S,1] = 8192
    float* prob = pred + NTOK;            // [B,H,S,S]

    build_kernel<<<NTOK, 128>>>(item_in, skill_in, label_in, item_ids,
                                skill_ids, item_emb, skill_emb);

    base_kernel<<<NTOK, 256>>>(ts, rel, l1, l2);

    // H = relu(X @ Win + b_in)
    sgemm_kernel<<<dim3(4, 128, 1), 256>>>(Win, b_in, Win, b_in, Win, b_in,
                                           512, 256, 0);
    // q,k,v in one launch (z-dispatch)
    sgemm_kernel<<<dim3(2, 128, 3), 256>>>(Wq, bq, Wk, bk, Wv, bv,
                                           256, 128, 1);

    attn_qk_kernel<<<dim3(NBH, SS/TQ), 256>>>(l1, l2, prob);

    pv_kernel<<<dim3(SS/64, NBH), 256>>>(prob);

    pred_kernel<<<NTOK, 128>>>(Wout, bout, pred);
}